// round 1
// baseline (speedup 1.0000x reference)
#include <cuda_runtime.h>

// Problem constants
#define NSRC 100000
#define NDST 100000
#define NE   500000
#define DIM  128
#define NLAY 2

// ---------------------------------------------------------------------------
// Scratch (device globals: allocation-free, graph-capture safe)
// ---------------------------------------------------------------------------
__device__ float g_hs[NSRC * DIM];      // h_s after layer 0
__device__ float g_hd[NDST * DIM];      // h_d after layer 0
__device__ float g_agg_s[NSRC * DIM];   // neighbor sums into src
__device__ float g_agg_d[NDST * DIM];   // neighbor sums into dst
__device__ float g_deg_s[NSRC];
__device__ float g_deg_d[NDST];
__device__ float g_inv_s[NSRC];
__device__ float g_inv_d[NDST];

// ---------------------------------------------------------------------------
// Packed f32x2 FMA (Blackwell): 2 FMA lanes per issue slot
// ---------------------------------------------------------------------------
__device__ __forceinline__ void ffma2(unsigned long long &c,
                                      const unsigned long long a,
                                      const unsigned long long b) {
    asm("fma.rn.f32x2 %0, %1, %2, %0;" : "+l"(c) : "l"(a), "l"(b));
}

__device__ __forceinline__ void atomic_add4(float* p, float4 v) {
#if !defined(__CUDA_ARCH__) || __CUDA_ARCH__ >= 900
    atomicAdd(reinterpret_cast<float4*>(p), v);
#else
    atomicAdd(p + 0, v.x); atomicAdd(p + 1, v.y);
    atomicAdd(p + 2, v.z); atomicAdd(p + 3, v.w);
#endif
}

// ---------------------------------------------------------------------------
// Degree kernels
// ---------------------------------------------------------------------------
__global__ void k_zero_deg() {
    int i = blockIdx.x * blockDim.x + threadIdx.x;
    if (i < NSRC) g_deg_s[i] = 0.0f;
    if (i < NDST) g_deg_d[i] = 0.0f;
}

__global__ void k_count_deg(const int* __restrict__ es, const int* __restrict__ ed) {
    int i = blockIdx.x * blockDim.x + threadIdx.x;
    if (i < NE) {
        atomicAdd(&g_deg_d[ed[i]], 1.0f);
        atomicAdd(&g_deg_s[es[i]], 1.0f);
    }
}

__global__ void k_inv_deg() {
    int i = blockIdx.x * blockDim.x + threadIdx.x;
    if (i < NSRC) g_inv_s[i] = 1.0f / fmaxf(g_deg_s[i], 1.0f);
    if (i < NDST) g_inv_d[i] = 1.0f / fmaxf(g_deg_d[i], 1.0f);
}

// ---------------------------------------------------------------------------
// Zero the aggregation buffers (both sides), float4 stores
// ---------------------------------------------------------------------------
__global__ void k_zero_agg() {
    int i = blockIdx.x * blockDim.x + threadIdx.x;   // float4 index
    const int n4 = NSRC * DIM / 4;
    float4 z = make_float4(0.f, 0.f, 0.f, 0.f);
    if (i < n4) {
        reinterpret_cast<float4*>(g_agg_s)[i] = z;
        reinterpret_cast<float4*>(g_agg_d)[i] = z;
    }
}

// ---------------------------------------------------------------------------
// Edge scatter: one warp per edge, both directions at once.
// lane L handles feature chunk [4L, 4L+4). Vector float4 atomics (sm_90+).
// ---------------------------------------------------------------------------
__global__ void __launch_bounds__(256) k_scatter(
    int layer,
    const float* __restrict__ x_src, const float* __restrict__ x_dst,
    const int* __restrict__ es, const int* __restrict__ ed)
{
    int w = (blockIdx.x * blockDim.x + threadIdx.x) >> 5;
    if (w >= NE) return;
    int lane = threadIdx.x & 31;
    const float* hs = layer ? g_hs : x_src;
    const float* hd = layer ? g_hd : x_dst;

    int s = __ldg(&es[w]);
    int d = __ldg(&ed[w]);
    int c = lane * 4;

    float4 vs = *reinterpret_cast<const float4*>(&hs[(size_t)s * DIM + c]);
    float4 vd = *reinterpret_cast<const float4*>(&hd[(size_t)d * DIM + c]);

    atomic_add4(&g_agg_d[(size_t)d * DIM + c], vs);   // src -> dst messages
    atomic_add4(&g_agg_s[(size_t)s * DIM + c], vd);   // dst -> src messages
}

// ---------------------------------------------------------------------------
// Fused SAGE GEMM: out = relu( A_self @ Wself^T + (agg * inv_deg) @ Wneigh^T + b )
// Treated as one M x 128 x K=256 GEMM. blockIdx.y selects direction:
//   y=0: ship  (updates dst side),  y=1: rev_ship (updates src side)
// BM=128, BN=128, BK=8, 256 threads, 8x8 microtile, packed f32x2 math.
// A values duplicated into pairs in smem so both FFMA2 operands come straight
// from LDS (no per-step packing movs).
// ---------------------------------------------------------------------------
__global__ void __launch_bounds__(256, 2) k_gemm(
    int layer,
    const float* __restrict__ x_src, const float* __restrict__ x_dst,
    const float* __restrict__ Wss,   // W_ship_self  [L][D][D]
    const float* __restrict__ Wsn,   // W_ship_neigh
    const float* __restrict__ bsh,   // b_ship [L][D]
    const float* __restrict__ Wrs,   // W_rev_self
    const float* __restrict__ Wrn,   // W_rev_neigh
    const float* __restrict__ brv,   // b_rev
    float* __restrict__ dout)        // harness output (h_s | h_d)
{
    const int M = NDST;  // == NSRC
    const float *Aself, *Aagg, *inv, *Wself, *Wneigh, *bias;
    float* out;
    if (blockIdx.y == 0) {           // -> new h_d
        Aself = layer ? g_hd : x_dst;
        Aagg  = g_agg_d;  inv = g_inv_d;
        Wself = Wss + layer * DIM * DIM;
        Wneigh= Wsn + layer * DIM * DIM;
        bias  = bsh + layer * DIM;
        out   = layer ? (dout + (size_t)NSRC * DIM) : g_hd;
    } else {                         // -> new h_s
        Aself = layer ? g_hs : x_src;
        Aagg  = g_agg_s;  inv = g_inv_s;
        Wself = Wrs + layer * DIM * DIM;
        Wneigh= Wrn + layer * DIM * DIM;
        bias  = brv + layer * DIM;
        out   = layer ? dout : g_hs;
    }

    __shared__ __align__(16) float Asd[2][8][2 * 128 + 4];  // duplicated pairs (a,a)
    __shared__ __align__(16) float Bs [2][8][132];          // Bs[k][n] = W[n][k]

    const int tid = threadIdx.x;
    const int tn  = tid & 15;        // 0..15 (n tile)
    const int tm  = tid >> 4;        // 0..15 (m tile)
    const int lm  = tid >> 1;        // 0..127 (load row)
    const int lk  = (tid & 1) * 4;   // 0 or 4 (load k quad)

    const int row0 = blockIdx.x * 128;
    int rA = row0 + lm; if (rA > M - 1) rA = M - 1;

    unsigned long long acc[8][4];
#pragma unroll
    for (int i = 0; i < 8; i++)
#pragma unroll
        for (int j = 0; j < 4; j++) acc[i][j] = 0ull;

    // Prologue: tile 0 (phase 0: A_self / W_self, k0 = 0)
    {
        float4 av = *reinterpret_cast<const float4*>(&Aself[(size_t)rA * DIM + lk]);
        float4 bv = *reinterpret_cast<const float4*>(&Wself[lm * DIM + lk]);
#pragma unroll
        for (int q = 0; q < 4; q++) {
            float a = (&av.x)[q];
            *reinterpret_cast<float2*>(&Asd[0][lk + q][2 * lm]) = make_float2(a, a);
            Bs[0][lk + q][lm] = (&bv.x)[q];
        }
    }
    __syncthreads();

#pragma unroll 1
    for (int t = 0; t < 32; t++) {
        const int buf = t & 1;
        float4 av, bv;
        const bool has_next = (t + 1 < 32);
        if (has_next) {
            int tp = t + 1;
            int ph = tp >> 4;                       // 0: self, 1: neigh
            int k0 = (tp & 15) * 8 + lk;
            const float* Ap = ph ? Aagg  : Aself;
            const float* Wp = ph ? Wneigh : Wself;
            av = *reinterpret_cast<const float4*>(&Ap[(size_t)rA * DIM + k0]);
            bv = *reinterpret_cast<const float4*>(&Wp[lm * DIM + k0]);
            if (ph) {
                float s = __ldg(&inv[rA]);
                av.x *= s; av.y *= s; av.z *= s; av.w *= s;
            }
        }

#pragma unroll
        for (int kk = 0; kk < 8; kk++) {
            const ulonglong2* ar =
                reinterpret_cast<const ulonglong2*>(&Asd[buf][kk][tm * 16]);
            ulonglong2 a01 = ar[0], a23 = ar[1], a45 = ar[2], a67 = ar[3];
            ulonglong2 b01 = *reinterpret_cast<const ulonglong2*>(&Bs[buf][kk][tn * 4]);
            ulonglong2 b23 = *reinterpret_cast<const ulonglong2*>(&Bs[buf][kk][64 + tn * 4]);
            unsigned long long a[8] = {a01.x, a01.y, a23.x, a23.y,
                                       a45.x, a45.y, a67.x, a67.y};
            unsigned long long b[4] = {b01.x, b01.y, b23.x, b23.y};
#pragma unroll
            for (int i = 0; i < 8; i++)
#pragma unroll
                for (int j = 0; j < 4; j++) ffma2(acc[i][j], a[i], b[j]);
        }

        if (has_next) {
            const int nbuf = buf ^ 1;
#pragma unroll
            for (int q = 0; q < 4; q++) {
                float a = (&av.x)[q];
                *reinterpret_cast<float2*>(&Asd[nbuf][lk + q][2 * lm]) = make_float2(a, a);
                Bs[nbuf][lk + q][lm] = (&bv.x)[q];
            }
        }
        __syncthreads();
    }

    // Epilogue: +bias, relu, store
    const int n0 = tn * 4;
    float4 bi0 = *reinterpret_cast<const float4*>(&bias[n0]);
    float4 bi1 = *reinterpret_cast<const float4*>(&bias[64 + n0]);
#pragma unroll
    for (int i = 0; i < 8; i++) {
        int r = row0 + tm * 8 + i;
        if (r < M) {
            float2 p0 = *reinterpret_cast<float2*>(&acc[i][0]);
            float2 p1 = *reinterpret_cast<float2*>(&acc[i][1]);
            float2 p2 = *reinterpret_cast<float2*>(&acc[i][2]);
            float2 p3 = *reinterpret_cast<float2*>(&acc[i][3]);
            float4 o0 = make_float4(fmaxf(p0.x + bi0.x, 0.f),
                                    fmaxf(p0.y + bi0.y, 0.f),
                                    fmaxf(p1.x + bi0.z, 0.f),
                                    fmaxf(p1.y + bi0.w, 0.f));
            float4 o1 = make_float4(fmaxf(p2.x + bi1.x, 0.f),
                                    fmaxf(p2.y + bi1.y, 0.f),
                                    fmaxf(p3.x + bi1.z, 0.f),
                                    fmaxf(p3.y + bi1.w, 0.f));
            *reinterpret_cast<float4*>(&out[(size_t)r * DIM + n0])      = o0;
            *reinterpret_cast<float4*>(&out[(size_t)r * DIM + 64 + n0]) = o1;
        }
    }
}

// ---------------------------------------------------------------------------
// Launch
// ---------------------------------------------------------------------------
extern "C" void kernel_launch(void* const* d_in, const int* in_sizes, int n_in,
                              void* d_out, int out_size)
{
    const float* x_src = (const float*)d_in[0];
    const float* x_dst = (const float*)d_in[1];
    const int*   e_src = (const int*)  d_in[2];
    const int*   e_dst = (const int*)  d_in[3];
    const float* Wss   = (const float*)d_in[4];
    const float* Wsn   = (const float*)d_in[5];
    const float* bsh   = (const float*)d_in[6];
    const float* Wrs   = (const float*)d_in[7];
    const float* Wrn   = (const float*)d_in[8];
    const float* brv   = (const float*)d_in[9];
    float* out = (float*)d_out;

    // Degrees (edge-structure only; recomputed every call for determinism rules)
    k_zero_deg<<<(NSRC + 255) / 256, 256>>>();
    k_count_deg<<<(NE + 255) / 256, 256>>>(e_src, e_dst);
    k_inv_deg<<<(NSRC + 255) / 256, 256>>>();

    dim3 ggrid((NDST + 127) / 128, 2);
    for (int layer = 0; layer < NLAY; layer++) {
        k_zero_agg<<<(NSRC * DIM / 4 + 255) / 256, 256>>>();
        k_scatter<<<(NE * 32 + 255) / 256, 256>>>(layer, x_src, x_dst, e_src, e_dst);
        k_gemm<<<ggrid, 256>>>(layer, x_src, x_dst,
                               Wss, Wsn, bsh, Wrs, Wrn, brv, out);
    }
}

// round 4
// speedup vs baseline: 1.3050x; 1.3050x over previous
#include <cuda_runtime.h>
#include <cuda_bf16.h>
#include <cstdint>

// Problem constants
#define NSRC 100000
#define NDST 100000
#define NE   500000
#define DIM  128
#define NLAY 2
#define TILES 782            // ceil(100000/128)

// ---------------------------------------------------------------------------
// Scratch (device globals: allocation-free, graph-capture safe)
// ---------------------------------------------------------------------------
__device__ float g_hs[NSRC * DIM];
__device__ float g_hd[NDST * DIM];
__device__ float g_agg_s[NSRC * DIM];
__device__ float g_agg_d[NDST * DIM];
__device__ float g_deg_s[NSRC];
__device__ float g_deg_d[NDST];
__device__ float g_inv_s[NSRC];
__device__ float g_inv_d[NDST];
// bf16 hi/lo weight images: [layer][dir][hi/lo][n=128][k=256] (k contiguous)
__device__ __nv_bfloat16 g_Bbf[NLAY][2][2][DIM * 256];

// ---------------------------------------------------------------------------
// Small kernels: degrees, agg zero, B precompute
// ---------------------------------------------------------------------------
__global__ void k_zero_deg() {
    int i = blockIdx.x * blockDim.x + threadIdx.x;
    if (i < NSRC) g_deg_s[i] = 0.0f;
    if (i < NDST) g_deg_d[i] = 0.0f;
}
__global__ void k_count_deg(const int* __restrict__ es, const int* __restrict__ ed) {
    int i = blockIdx.x * blockDim.x + threadIdx.x;
    if (i < NE) {
        atomicAdd(&g_deg_d[ed[i]], 1.0f);
        atomicAdd(&g_deg_s[es[i]], 1.0f);
    }
}
__global__ void k_inv_deg() {
    int i = blockIdx.x * blockDim.x + threadIdx.x;
    if (i < NSRC) g_inv_s[i] = 1.0f / fmaxf(g_deg_s[i], 1.0f);
    if (i < NDST) g_inv_d[i] = 1.0f / fmaxf(g_deg_d[i], 1.0f);
}
__global__ void k_zero_agg() {
    int i = blockIdx.x * blockDim.x + threadIdx.x;
    const int n4 = NSRC * DIM / 4;
    float4 z = make_float4(0.f, 0.f, 0.f, 0.f);
    if (i < n4) {
        reinterpret_cast<float4*>(g_agg_s)[i] = z;
        reinterpret_cast<float4*>(g_agg_d)[i] = z;
    }
}
// B = [W_self | W_neigh] concat along K: B[n][k], k in [0,256)
__global__ void k_prep_B(const float* __restrict__ Wss, const float* __restrict__ Wsn,
                         const float* __restrict__ Wrs, const float* __restrict__ Wrn) {
    int l = blockIdx.x >> 1, d = blockIdx.x & 1;
    const float* Wself  = (d == 0 ? Wss : Wrs) + l * DIM * DIM;
    const float* Wneigh = (d == 0 ? Wsn : Wrn) + l * DIM * DIM;
    for (int i = threadIdx.x; i < DIM * 256; i += blockDim.x) {
        int n = i >> 8;
        int k = i & 255;
        float v = (k < DIM) ? Wself[n * DIM + k] : Wneigh[n * DIM + (k - DIM)];
        __nv_bfloat16 hi = __float2bfloat16(v);
        __nv_bfloat16 lo = __float2bfloat16(v - __bfloat162float(hi));
        g_Bbf[l][d][0][i] = hi;
        g_Bbf[l][d][1][i] = lo;
    }
}

// ---------------------------------------------------------------------------
// Edge scatter: one warp per edge, both directions, float4 atomics
// ---------------------------------------------------------------------------
__global__ void __launch_bounds__(256) k_scatter(
    int layer,
    const float* __restrict__ x_src, const float* __restrict__ x_dst,
    const int* __restrict__ es, const int* __restrict__ ed)
{
    int w = (blockIdx.x * blockDim.x + threadIdx.x) >> 5;
    if (w >= NE) return;
    int lane = threadIdx.x & 31;
    const float* hs = layer ? g_hs : x_src;
    const float* hd = layer ? g_hd : x_dst;
    int s = __ldg(&es[w]);
    int d = __ldg(&ed[w]);
    int c = lane * 4;
    float4 vs = *reinterpret_cast<const float4*>(&hs[(size_t)s * DIM + c]);
    float4 vd = *reinterpret_cast<const float4*>(&hd[(size_t)d * DIM + c]);
    atomicAdd(reinterpret_cast<float4*>(&g_agg_d[(size_t)d * DIM + c]), vs);
    atomicAdd(reinterpret_cast<float4*>(&g_agg_s[(size_t)s * DIM + c]), vd);
}

// ---------------------------------------------------------------------------
// mma.sync bf16 fused SAGE GEMM (3-term hi/lo split).
// out = relu( [h_self | agg*inv] @ [Wself;Wneigh]^T + b ),  M x 128 x K=256.
// CTA tile 128x128, 8 warps (2m x 4n), warp tile 64x32, mma m16n8k16.
// K processed in 4 chunks of 64; per chunk 3 terms: Ah*Bh, Al*Bh, Ah*Bl.
// ---------------------------------------------------------------------------
#define SPAD 72                      // bf16 row pitch in smem (64 + 8 pad)
#define A_HI 0
#define A_LO (128 * SPAD)
#define B_HI (2 * 128 * SPAD)
#define B_LO (3 * 128 * SPAD)
#define SM_ELEMS (4 * 128 * SPAD)               // bf16 elements
#define SM_BIAS_B (SM_ELEMS * 2)                // byte offset of bias
#define SM_TOTAL (SM_BIAS_B + DIM * 4)

__device__ __forceinline__ uint32_t smem_u32(const void* p) {
    uint32_t a;
    asm("{ .reg .u64 t; cvta.to.shared.u64 t, %1; cvt.u32.u64 %0, t; }" : "=r"(a) : "l"(p));
    return a;
}

#define LDSM_X4(r, addr) \
    asm volatile("ldmatrix.sync.aligned.m8n8.x4.shared.b16 {%0,%1,%2,%3}, [%4];" \
        : "=r"((r)[0]), "=r"((r)[1]), "=r"((r)[2]), "=r"((r)[3]) : "r"(addr))

#define MMA_BF16(c, a, b0, b1) \
    asm volatile("mma.sync.aligned.m16n8k16.row.col.f32.bf16.bf16.f32 " \
        "{%0,%1,%2,%3}, {%4,%5,%6,%7}, {%8,%9}, {%0,%1,%2,%3};" \
        : "+f"((c)[0]), "+f"((c)[1]), "+f"((c)[2]), "+f"((c)[3]) \
        : "r"((a)[0]), "r"((a)[1]), "r"((a)[2]), "r"((a)[3]), "r"(b0), "r"(b1))

__global__ void __launch_bounds__(256, 2) k_gemm(
    int layer,
    const float* __restrict__ xs, const float* __restrict__ xd,
    const float* __restrict__ bsh, const float* __restrict__ brv,
    float* __restrict__ dout)
{
    extern __shared__ __nv_bfloat16 sm[];
    float* sbias = (float*)((char*)sm + SM_BIAS_B);

    const int tid  = threadIdx.x;
    const int wid  = tid >> 5, lane = tid & 31;
    const int dir  = blockIdx.y;
    const int wm   = wid & 1;            // 0..1  (64 rows each)
    const int wn   = wid >> 1;           // 0..3  (32 cols each)

    const float *Aself, *Aagg, *inv, *bias;
    float* out;
    if (dir == 0) {                      // -> new h_d
        Aself = layer ? g_hd : xd;  Aagg = g_agg_d;  inv = g_inv_d;
        bias  = bsh + layer * DIM;
        out   = layer ? (dout + (size_t)NSRC * DIM) : g_hd;
    } else {                             // -> new h_s
        Aself = layer ? g_hs : xs;  Aagg = g_agg_s;  inv = g_inv_s;
        bias  = brv + layer * DIM;
        out   = layer ? dout : g_hs;
    }
    const __nv_bfloat16* Bh = g_Bbf[layer][dir][0];
    const __nv_bfloat16* Bl = g_Bbf[layer][dir][1];

    if (tid < DIM) sbias[tid] = bias[tid];

    const int row0 = blockIdx.x * 128;

    // A loader mapping: 2 threads per row, 32 floats each
    const int lrow  = tid >> 1;
    const int lhalf = (tid & 1) * 32;
    int rclamp = row0 + lrow; if (rclamp > NSRC - 1) rclamp = NSRC - 1;
    const float invr = inv[rclamp];

    // ldmatrix per-thread address components (bf16-element offsets)
    const uint32_t smb = smem_u32(sm);
    const int a_row_off = (wm * 64 + (lane & 15)) * SPAD + (lane >> 4) * 8;
    const int b_row_off = (wn * 32 + (lane & 7) + (lane >> 4) * 8) * SPAD + ((lane >> 3) & 1) * 8;

    float acc[4][4][4];
#pragma unroll
    for (int i = 0; i < 4; i++)
#pragma unroll
        for (int j = 0; j < 4; j++)
#pragma unroll
            for (int q = 0; q < 4; q++) acc[i][j][q] = 0.f;

#pragma unroll 1
    for (int kc = 0; kc < 4; kc++) {
        __syncthreads();
        // --- load A chunk (fp32 -> bf16 hi/lo) ---
        {
            const float* src = ((kc < 2) ? Aself : Aagg) + (size_t)rclamp * DIM + (kc & 1) * 64 + lhalf;
            const float sc = (kc < 2) ? 1.0f : invr;
            __nv_bfloat16* ah = sm + A_HI + lrow * SPAD + lhalf;
            __nv_bfloat16* al = sm + A_LO + lrow * SPAD + lhalf;
#pragma unroll
            for (int q = 0; q < 8; q++) {
                float4 v = __ldg((const float4*)src + q);
                v.x *= sc; v.y *= sc; v.z *= sc; v.w *= sc;
                uint32_t h0, h1, l0, l1;
                asm("cvt.rn.bf16x2.f32 %0, %1, %2;" : "=r"(h0) : "f"(v.y), "f"(v.x));
                float hx = __uint_as_float(h0 << 16);
                float hy = __uint_as_float(h0 & 0xffff0000u);
                asm("cvt.rn.bf16x2.f32 %0, %1, %2;" : "=r"(l0) : "f"(v.y - hy), "f"(v.x - hx));
                asm("cvt.rn.bf16x2.f32 %0, %1, %2;" : "=r"(h1) : "f"(v.w), "f"(v.z));
                float hz = __uint_as_float(h1 << 16);
                float hw = __uint_as_float(h1 & 0xffff0000u);
                asm("cvt.rn.bf16x2.f32 %0, %1, %2;" : "=r"(l1) : "f"(v.w - hw), "f"(v.z - hz));
                *(uint2*)(ah + 4 * q) = make_uint2(h0, h1);
                *(uint2*)(al + 4 * q) = make_uint2(l0, l1);
            }
        }
        // --- load B chunk (bf16 copy) --- thread t: n = t>>1, 32 k-values
        // 4 x uint4 (8 bf16 each) = 32 contiguous bf16, stored contiguously.
        {
            const int bn = tid >> 1;
            const int bk = (tid & 1) * 32;
            const uint4* gh = (const uint4*)(Bh + bn * 256 + kc * 64 + bk);
            const uint4* gl = (const uint4*)(Bl + bn * 256 + kc * 64 + bk);
            __nv_bfloat16* dh = sm + B_HI + bn * SPAD + bk;
            __nv_bfloat16* dl = sm + B_LO + bn * SPAD + bk;
#pragma unroll
            for (int q = 0; q < 4; q++) {
                uint4 vh = __ldg(gh + q);
                uint4 vl = __ldg(gl + q);
                *(uint4*)(dh + 8 * q) = vh;
                *(uint4*)(dl + 8 * q) = vl;
            }
        }
        __syncthreads();

        // --- compute: 3 terms x 4 k16 steps ---
#pragma unroll
        for (int term = 0; term < 3; term++) {
            const uint32_t aBase = smb + 2 * ((term == 1 ? A_LO : A_HI) + a_row_off);
            const uint32_t bBase = smb + 2 * ((term == 2 ? B_LO : B_HI) + b_row_off);
#pragma unroll
            for (int k16 = 0; k16 < 4; k16++) {
                uint32_t a[4][4], b[2][4];
#pragma unroll
                for (int mt = 0; mt < 4; mt++)
                    LDSM_X4(a[mt], aBase + 2 * (mt * 16 * SPAD + k16 * 16));
#pragma unroll
                for (int p = 0; p < 2; p++)
                    LDSM_X4(b[p], bBase + 2 * (p * 16 * SPAD + k16 * 16));
#pragma unroll
                for (int mt = 0; mt < 4; mt++) {
#pragma unroll
                    for (int nt = 0; nt < 4; nt++)
                        MMA_BF16(acc[mt][nt], a[mt], b[nt >> 1][(nt & 1) * 2], b[nt >> 1][(nt & 1) * 2 + 1]);
                }
            }
        }
    }

    // --- epilogue: +bias, relu, store ---
    const int ebase_r = row0 + wm * 64 + (lane >> 2);
    const int ebase_c = wn * 32 + (lane & 3) * 2;
#pragma unroll
    for (int mt = 0; mt < 4; mt++) {
#pragma unroll
        for (int nt = 0; nt < 4; nt++) {
            const int c = ebase_c + nt * 8;
            const float b0 = sbias[c], b1 = sbias[c + 1];
            int r = ebase_r + mt * 16;
            if (r < NDST) {
                float2 o = make_float2(fmaxf(acc[mt][nt][0] + b0, 0.f),
                                       fmaxf(acc[mt][nt][1] + b1, 0.f));
                *(float2*)&out[(size_t)r * DIM + c] = o;
            }
            if (r + 8 < NDST) {
                float2 o = make_float2(fmaxf(acc[mt][nt][2] + b0, 0.f),
                                       fmaxf(acc[mt][nt][3] + b1, 0.f));
                *(float2*)&out[(size_t)(r + 8) * DIM + c] = o;
            }
        }
    }
}

// ---------------------------------------------------------------------------
// Launch
// ---------------------------------------------------------------------------
extern "C" void kernel_launch(void* const* d_in, const int* in_sizes, int n_in,
                              void* d_out, int out_size)
{
    const float* x_src = (const float*)d_in[0];
    const float* x_dst = (const float*)d_in[1];
    const int*   e_src = (const int*)  d_in[2];
    const int*   e_dst = (const int*)  d_in[3];
    const float* Wss   = (const float*)d_in[4];
    const float* Wsn   = (const float*)d_in[5];
    const float* bsh   = (const float*)d_in[6];
    const float* Wrs   = (const float*)d_in[7];
    const float* Wrn   = (const float*)d_in[8];
    const float* brv   = (const float*)d_in[9];
    float* out = (float*)d_out;

    cudaFuncSetAttribute(k_gemm, cudaFuncAttributeMaxDynamicSharedMemorySize, SM_TOTAL);

    k_zero_deg<<<(NSRC + 255) / 256, 256>>>();
    k_count_deg<<<(NE + 255) / 256, 256>>>(e_src, e_dst);
    k_inv_deg<<<(NSRC + 255) / 256, 256>>>();
    k_prep_B<<<4, 256>>>(Wss, Wsn, Wrs, Wrn);

    for (int layer = 0; layer < NLAY; layer++) {
        k_zero_agg<<<(NSRC * DIM / 4 + 255) / 256, 256>>>();
        k_scatter<<<(NE * 32 + 255) / 256, 256>>>(layer, x_src, x_dst, e_src, e_dst);
        k_gemm<<<dim3(TILES, 2), 256, SM_TOTAL>>>(layer, x_src, x_dst, bsh, brv, out);
    }
}

// round 5
// speedup vs baseline: 1.5873x; 1.2163x over previous
#include <cuda_runtime.h>
#include <cuda_bf16.h>
#include <cstdint>

// Problem constants
#define NSRC 100000
#define NDST 100000
#define NE   500000
#define DIM  128
#define NLAY 2
#define TILES 782            // ceil(100000/128)
#define SCAN_BLK 98          // ceil(100000/1024)

// ---------------------------------------------------------------------------
// Scratch (device globals: allocation-free, graph-capture safe)
// ---------------------------------------------------------------------------
__device__ float g_hs[NSRC * DIM];
__device__ float g_hd[NDST * DIM];
__device__ float g_agg_s[NSRC * DIM];   // mean-aggregated neighbor features
__device__ float g_agg_d[NDST * DIM];
// CSR structures (rebuilt every call; graph static within a call)
__device__ int g_off_d[NDST + 1];
__device__ int g_off_s[NSRC + 1];
__device__ int g_cur_d[NDST];           // counts, then cursors
__device__ int g_cur_s[NSRC];
__device__ int g_adj_d[NE];             // src ids grouped by dst
__device__ int g_adj_s[NE];             // dst ids grouped by src
__device__ int g_part[2][128];          // block partial sums for scan
// bf16 hi/lo weight images: [layer][dir][hi/lo][n=128][k=256] (k contiguous)
__device__ __nv_bfloat16 g_Bbf[NLAY][2][2][DIM * 256];

// ---------------------------------------------------------------------------
// CSR build: histogram -> 2-level exclusive scan -> placement
// ---------------------------------------------------------------------------
__global__ void k_zero_cnt() {
    int i = blockIdx.x * blockDim.x + threadIdx.x;
    if (i < NDST) { g_cur_d[i] = 0; g_cur_s[i] = 0; }
}
__global__ void k_count(const int* __restrict__ es, const int* __restrict__ ed) {
    int i = blockIdx.x * blockDim.x + threadIdx.x;
    if (i < NE) {
        atomicAdd(&g_cur_d[ed[i]], 1);
        atomicAdd(&g_cur_s[es[i]], 1);
    }
}
__global__ void k_blocksum() {
    const int a = blockIdx.y;
    const int* cnt = a ? g_cur_s : g_cur_d;
    __shared__ int sm[256];
    int base = blockIdx.x * 1024 + threadIdx.x * 4;
    int s = 0;
#pragma unroll
    for (int q = 0; q < 4; q++) { int i = base + q; if (i < NDST) s += cnt[i]; }
    sm[threadIdx.x] = s; __syncthreads();
    for (int st = 128; st > 0; st >>= 1) {
        if (threadIdx.x < st) sm[threadIdx.x] += sm[threadIdx.x + st];
        __syncthreads();
    }
    if (threadIdx.x == 0) g_part[a][blockIdx.x] = sm[0];
}
__global__ void k_scanpart() {
    __shared__ int sm[128];
    int t = threadIdx.x;
    for (int a = 0; a < 2; a++) {
        int v = (t < SCAN_BLK) ? g_part[a][t] : 0;
        sm[t] = v; __syncthreads();
        for (int st = 1; st < 128; st <<= 1) {
            int u = (t >= st) ? sm[t - st] : 0;
            __syncthreads();
            sm[t] += u;
            __syncthreads();
        }
        if (t < SCAN_BLK) g_part[a][t] = sm[t] - v;   // exclusive
        __syncthreads();
    }
}
__global__ void k_write_off() {
    const int a = blockIdx.y;
    int* cnt = a ? g_cur_s : g_cur_d;
    int* off = a ? g_off_s : g_off_d;
    __shared__ int sm[256];
    const int t = threadIdx.x;
    const int i0 = blockIdx.x * 1024 + t * 4;
    int c[4]; int ts = 0;
#pragma unroll
    for (int q = 0; q < 4; q++) { int i = i0 + q; c[q] = (i < NDST) ? cnt[i] : 0; ts += c[q]; }
    sm[t] = ts; __syncthreads();
    for (int st = 1; st < 256; st <<= 1) {
        int u = (t >= st) ? sm[t - st] : 0;
        __syncthreads();
        sm[t] += u;
        __syncthreads();
    }
    int excl = sm[t] - ts + g_part[a][blockIdx.x];
#pragma unroll
    for (int q = 0; q < 4; q++) {
        int i = i0 + q;
        if (i < NDST) {
            off[i] = excl;
            cnt[i] = excl;                       // cursor init
            if (i == NDST - 1) off[NDST] = excl + c[q];  // == NE
            excl += c[q];
        }
    }
}
__global__ void k_place(const int* __restrict__ es, const int* __restrict__ ed) {
    int i = blockIdx.x * blockDim.x + threadIdx.x;
    if (i >= NE) return;
    int s = es[i], d = ed[i];
    int pd = atomicAdd(&g_cur_d[d], 1);
    g_adj_d[pd] = s;
    int ps = atomicAdd(&g_cur_s[s], 1);
    g_adj_s[ps] = d;
}

// ---------------------------------------------------------------------------
// B = [W_self | W_neigh] concat along K: B[n][k], k in [0,256)
// ---------------------------------------------------------------------------
__global__ void k_prep_B(const float* __restrict__ Wss, const float* __restrict__ Wsn,
                         const float* __restrict__ Wrs, const float* __restrict__ Wrn) {
    int l = blockIdx.x >> 1, d = blockIdx.x & 1;
    const float* Wself  = (d == 0 ? Wss : Wrs) + l * DIM * DIM;
    const float* Wneigh = (d == 0 ? Wsn : Wrn) + l * DIM * DIM;
    for (int i = blockIdx.y * blockDim.x + threadIdx.x; i < DIM * 256; i += blockDim.x * gridDim.y) {
        int n = i >> 8;
        int k = i & 255;
        float v = (k < DIM) ? Wself[n * DIM + k] : Wneigh[n * DIM + (k - DIM)];
        __nv_bfloat16 hi = __float2bfloat16(v);
        __nv_bfloat16 lo = __float2bfloat16(v - __bfloat162float(hi));
        g_Bbf[l][d][0][i] = hi;
        g_Bbf[l][d][1][i] = lo;
    }
}

// ---------------------------------------------------------------------------
// CSR gather: one warp per (node, dir). Mean folded in. No atomics, no zeroing.
// ---------------------------------------------------------------------------
__global__ void __launch_bounds__(256) k_gather(
    int layer, const float* __restrict__ xs, const float* __restrict__ xd)
{
    int w = (blockIdx.x * blockDim.x + threadIdx.x) >> 5;
    if (w >= 2 * NDST) return;
    const int lane = threadIdx.x & 31;
    int node, dir;
    if (w < NDST) { node = w; dir = 0; } else { node = w - NDST; dir = 1; }

    const int *off, *adj; const float* feat; float* agg;
    if (dir == 0) { off = g_off_d; adj = g_adj_d; feat = layer ? g_hs : xs; agg = g_agg_d; }
    else          { off = g_off_s; adj = g_adj_s; feat = layer ? g_hd : xd; agg = g_agg_s; }

    const int b = off[node], e = off[node + 1];
    const int c = lane * 4;
    float4 acc = make_float4(0.f, 0.f, 0.f, 0.f);
    int j = b;
    for (; j + 1 < e; j += 2) {                  // 2 loads in flight
        int r0 = __ldg(&adj[j]);
        int r1 = __ldg(&adj[j + 1]);
        float4 v0 = *reinterpret_cast<const float4*>(&feat[(size_t)r0 * DIM + c]);
        float4 v1 = *reinterpret_cast<const float4*>(&feat[(size_t)r1 * DIM + c]);
        acc.x += v0.x + v1.x; acc.y += v0.y + v1.y;
        acc.z += v0.z + v1.z; acc.w += v0.w + v1.w;
    }
    if (j < e) {
        int r0 = __ldg(&adj[j]);
        float4 v0 = *reinterpret_cast<const float4*>(&feat[(size_t)r0 * DIM + c]);
        acc.x += v0.x; acc.y += v0.y; acc.z += v0.z; acc.w += v0.w;
    }
    const float s = 1.0f / fmaxf((float)(e - b), 1.0f);
    acc.x *= s; acc.y *= s; acc.z *= s; acc.w *= s;
    *reinterpret_cast<float4*>(&agg[(size_t)node * DIM + c]) = acc;
}

// ---------------------------------------------------------------------------
// mma.sync bf16 fused SAGE GEMM (3-term hi/lo split).
// out = relu( [h_self | agg_mean] @ [Wself;Wneigh]^T + b ),  M x 128 x K=256.
// CTA tile 128x128, 8 warps (2m x 4n), warp tile 64x32, mma m16n8k16.
// ---------------------------------------------------------------------------
#define SPAD 72                      // bf16 row pitch in smem (64 + 8 pad)
#define A_HI 0
#define A_LO (128 * SPAD)
#define B_HI (2 * 128 * SPAD)
#define B_LO (3 * 128 * SPAD)
#define SM_ELEMS (4 * 128 * SPAD)               // bf16 elements
#define SM_BIAS_B (SM_ELEMS * 2)                // byte offset of bias
#define SM_TOTAL (SM_BIAS_B + DIM * 4)

__device__ __forceinline__ uint32_t smem_u32(const void* p) {
    uint32_t a;
    asm("{ .reg .u64 t; cvta.to.shared.u64 t, %1; cvt.u32.u64 %0, t; }" : "=r"(a) : "l"(p));
    return a;
}

#define LDSM_X4(r, addr) \
    asm volatile("ldmatrix.sync.aligned.m8n8.x4.shared.b16 {%0,%1,%2,%3}, [%4];" \
        : "=r"((r)[0]), "=r"((r)[1]), "=r"((r)[2]), "=r"((r)[3]) : "r"(addr))

#define MMA_BF16(c, a, b0, b1) \
    asm volatile("mma.sync.aligned.m16n8k16.row.col.f32.bf16.bf16.f32 " \
        "{%0,%1,%2,%3}, {%4,%5,%6,%7}, {%8,%9}, {%0,%1,%2,%3};" \
        : "+f"((c)[0]), "+f"((c)[1]), "+f"((c)[2]), "+f"((c)[3]) \
        : "r"((a)[0]), "r"((a)[1]), "r"((a)[2]), "r"((a)[3]), "r"(b0), "r"(b1))

__global__ void __launch_bounds__(256, 2) k_gemm(
    int layer,
    const float* __restrict__ xs, const float* __restrict__ xd,
    const float* __restrict__ bsh, const float* __restrict__ brv,
    float* __restrict__ dout)
{
    extern __shared__ __nv_bfloat16 sm[];
    float* sbias = (float*)((char*)sm + SM_BIAS_B);

    const int tid  = threadIdx.x;
    const int wid  = tid >> 5, lane = tid & 31;
    const int dir  = blockIdx.y;
    const int wm   = wid & 1;            // 0..1  (64 rows each)
    const int wn   = wid >> 1;           // 0..3  (32 cols each)

    const float *Aself, *Aagg, *bias;
    float* out;
    if (dir == 0) {                      // -> new h_d
        Aself = layer ? g_hd : xd;  Aagg = g_agg_d;
        bias  = bsh + layer * DIM;
        out   = layer ? (dout + (size_t)NSRC * DIM) : g_hd;
    } else {                             // -> new h_s
        Aself = layer ? g_hs : xs;  Aagg = g_agg_s;
        bias  = brv + layer * DIM;
        out   = layer ? dout : g_hs;
    }
    const __nv_bfloat16* Bh = g_Bbf[layer][dir][0];
    const __nv_bfloat16* Bl = g_Bbf[layer][dir][1];

    if (tid < DIM) sbias[tid] = bias[tid];

    const int row0 = blockIdx.x * 128;

    // A loader mapping: 2 threads per row, 32 floats each
    const int lrow  = tid >> 1;
    const int lhalf = (tid & 1) * 32;
    int rclamp = row0 + lrow; if (rclamp > NSRC - 1) rclamp = NSRC - 1;

    // ldmatrix per-thread address components (bf16-element offsets)
    const uint32_t smb = smem_u32(sm);
    const int a_row_off = (wm * 64 + (lane & 15)) * SPAD + (lane >> 4) * 8;
    const int b_row_off = (wn * 32 + (lane & 7) + (lane >> 4) * 8) * SPAD + ((lane >> 3) & 1) * 8;

    float acc[4][4][4];
#pragma unroll
    for (int i = 0; i < 4; i++)
#pragma unroll
        for (int j = 0; j < 4; j++)
#pragma unroll
            for (int q = 0; q < 4; q++) acc[i][j][q] = 0.f;

#pragma unroll 1
    for (int kc = 0; kc < 4; kc++) {
        __syncthreads();
        // --- load A chunk (fp32 -> bf16 hi/lo) ---
        {
            const float* src = ((kc < 2) ? Aself : Aagg) + (size_t)rclamp * DIM + (kc & 1) * 64 + lhalf;
            __nv_bfloat16* ah = sm + A_HI + lrow * SPAD + lhalf;
            __nv_bfloat16* al = sm + A_LO + lrow * SPAD + lhalf;
#pragma unroll
            for (int q = 0; q < 8; q++) {
                float4 v = __ldg((const float4*)src + q);
                uint32_t h0, h1, l0, l1;
                asm("cvt.rn.bf16x2.f32 %0, %1, %2;" : "=r"(h0) : "f"(v.y), "f"(v.x));
                float hx = __uint_as_float(h0 << 16);
                float hy = __uint_as_float(h0 & 0xffff0000u);
                asm("cvt.rn.bf16x2.f32 %0, %1, %2;" : "=r"(l0) : "f"(v.y - hy), "f"(v.x - hx));
                asm("cvt.rn.bf16x2.f32 %0, %1, %2;" : "=r"(h1) : "f"(v.w), "f"(v.z));
                float hz = __uint_as_float(h1 << 16);
                float hw = __uint_as_float(h1 & 0xffff0000u);
                asm("cvt.rn.bf16x2.f32 %0, %1, %2;" : "=r"(l1) : "f"(v.w - hw), "f"(v.z - hz));
                *(uint2*)(ah + 4 * q) = make_uint2(h0, h1);
                *(uint2*)(al + 4 * q) = make_uint2(l0, l1);
            }
        }
        // --- load B chunk: 4 x uint4 (8 bf16) = 32 contiguous bf16 per thread ---
        {
            const int bn = tid >> 1;
            const int bk = (tid & 1) * 32;
            const uint4* gh = (const uint4*)(Bh + bn * 256 + kc * 64 + bk);
            const uint4* gl = (const uint4*)(Bl + bn * 256 + kc * 64 + bk);
            __nv_bfloat16* dh = sm + B_HI + bn * SPAD + bk;
            __nv_bfloat16* dl = sm + B_LO + bn * SPAD + bk;
#pragma unroll
            for (int q = 0; q < 4; q++) {
                uint4 vh = __ldg(gh + q);
                uint4 vl = __ldg(gl + q);
                *(uint4*)(dh + 8 * q) = vh;
                *(uint4*)(dl + 8 * q) = vl;
            }
        }
        __syncthreads();

        // --- compute: 3 terms x 4 k16 steps ---
#pragma unroll
        for (int term = 0; term < 3; term++) {
            const uint32_t aBase = smb + 2 * ((term == 1 ? A_LO : A_HI) + a_row_off);
            const uint32_t bBase = smb + 2 * ((term == 2 ? B_LO : B_HI) + b_row_off);
#pragma unroll
            for (int k16 = 0; k16 < 4; k16++) {
                uint32_t a[4][4], b[2][4];
#pragma unroll
                for (int mt = 0; mt < 4; mt++)
                    LDSM_X4(a[mt], aBase + 2 * (mt * 16 * SPAD + k16 * 16));
#pragma unroll
                for (int p = 0; p < 2; p++)
                    LDSM_X4(b[p], bBase + 2 * (p * 16 * SPAD + k16 * 16));
#pragma unroll
                for (int mt = 0; mt < 4; mt++) {
#pragma unroll
                    for (int nt = 0; nt < 4; nt++)
                        MMA_BF16(acc[mt][nt], a[mt], b[nt >> 1][(nt & 1) * 2], b[nt >> 1][(nt & 1) * 2 + 1]);
                }
            }
        }
    }

    // --- epilogue: +bias, relu, store ---
    const int ebase_r = row0 + wm * 64 + (lane >> 2);
    const int ebase_c = wn * 32 + (lane & 3) * 2;
#pragma unroll
    for (int mt = 0; mt < 4; mt++) {
#pragma unroll
        for (int nt = 0; nt < 4; nt++) {
            const int c = ebase_c + nt * 8;
            const float b0 = sbias[c], b1 = sbias[c + 1];
            int r = ebase_r + mt * 16;
            if (r < NDST) {
                float2 o = make_float2(fmaxf(acc[mt][nt][0] + b0, 0.f),
                                       fmaxf(acc[mt][nt][1] + b1, 0.f));
                *(float2*)&out[(size_t)r * DIM + c] = o;
            }
            if (r + 8 < NDST) {
                float2 o = make_float2(fmaxf(acc[mt][nt][2] + b0, 0.f),
                                       fmaxf(acc[mt][nt][3] + b1, 0.f));
                *(float2*)&out[(size_t)(r + 8) * DIM + c] = o;
            }
        }
    }
}

// ---------------------------------------------------------------------------
// Launch
// ---------------------------------------------------------------------------
extern "C" void kernel_launch(void* const* d_in, const int* in_sizes, int n_in,
                              void* d_out, int out_size)
{
    const float* x_src = (const float*)d_in[0];
    const float* x_dst = (const float*)d_in[1];
    const int*   e_src = (const int*)  d_in[2];
    const int*   e_dst = (const int*)  d_in[3];
    const float* Wss   = (const float*)d_in[4];
    const float* Wsn   = (const float*)d_in[5];
    const float* bsh   = (const float*)d_in[6];
    const float* Wrs   = (const float*)d_in[7];
    const float* Wrn   = (const float*)d_in[8];
    const float* brv   = (const float*)d_in[9];
    float* out = (float*)d_out;

    cudaFuncSetAttribute(k_gemm, cudaFuncAttributeMaxDynamicSharedMemorySize, SM_TOTAL);

    // CSR build (once per call; graph static)
    k_zero_cnt<<<(NDST + 255) / 256, 256>>>();
    k_count<<<(NE + 255) / 256, 256>>>(e_src, e_dst);
    k_blocksum<<<dim3(SCAN_BLK, 2), 256>>>();
    k_scanpart<<<1, 128>>>();
    k_write_off<<<dim3(SCAN_BLK, 2), 256>>>();
    k_place<<<(NE + 255) / 256, 256>>>(e_src, e_dst);
    k_prep_B<<<dim3(4, 8), 256>>>(Wss, Wsn, Wrs, Wrn);

    for (int layer = 0; layer < NLAY; layer++) {
        k_gather<<<(2 * NDST * 32 + 255) / 256, 256>>>(layer, x_src, x_dst);
        k_gemm<<<dim3(TILES, 2), 256, SM_TOTAL>>>(layer, x_src, x_dst, bsh, brv, out);
    }
}

// round 6
// speedup vs baseline: 2.0769x; 1.3085x over previous
#include <cuda_runtime.h>
#include <cuda_bf16.h>
#include <cstdint>

// Problem constants
#define NSRC 100000
#define NDST 100000
#define NE   500000
#define DIM  128
#define NLAY 2
#define TILES 782            // ceil(100000/128)
#define PCTAS 74             // persistent CTAs per direction
#define SCAN_BLK 98          // ceil(100000/1024)

// ---------------------------------------------------------------------------
// Scratch (device globals: allocation-free, graph-capture safe)
// ---------------------------------------------------------------------------
// bf16 hi/lo feature planes (h after layer0, agg per dir)
__device__ __nv_bfloat16 g_hs_hi[NSRC * DIM], g_hs_lo[NSRC * DIM];
__device__ __nv_bfloat16 g_hd_hi[NDST * DIM], g_hd_lo[NDST * DIM];
__device__ __nv_bfloat16 g_aggs_hi[NSRC * DIM], g_aggs_lo[NSRC * DIM];
__device__ __nv_bfloat16 g_aggd_hi[NDST * DIM], g_aggd_lo[NDST * DIM];
// CSR structures
__device__ int g_off_d[NDST + 1];
__device__ int g_off_s[NSRC + 1];
__device__ int g_cur_d[NDST];
__device__ int g_cur_s[NSRC];
__device__ int g_adj_d[NE];
__device__ int g_adj_s[NE];
__device__ int g_part[2][128];
// bf16 hi/lo weight images: [layer][dir][hi/lo][n=128][k=256] (k contiguous)
__device__ __nv_bfloat16 g_Bbf[NLAY][2][2][DIM * 256];

// ---------------------------------------------------------------------------
// CSR build: histogram -> 2-level exclusive scan -> placement
// ---------------------------------------------------------------------------
__global__ void k_zero_cnt() {
    int i = blockIdx.x * blockDim.x + threadIdx.x;
    if (i < NDST) { g_cur_d[i] = 0; g_cur_s[i] = 0; }
}
__global__ void k_count(const int* __restrict__ es, const int* __restrict__ ed) {
    int i = blockIdx.x * blockDim.x + threadIdx.x;
    if (i < NE) {
        atomicAdd(&g_cur_d[ed[i]], 1);
        atomicAdd(&g_cur_s[es[i]], 1);
    }
}
__global__ void k_blocksum() {
    const int a = blockIdx.y;
    const int* cnt = a ? g_cur_s : g_cur_d;
    __shared__ int sm[256];
    int base = blockIdx.x * 1024 + threadIdx.x * 4;
    int s = 0;
#pragma unroll
    for (int q = 0; q < 4; q++) { int i = base + q; if (i < NDST) s += cnt[i]; }
    sm[threadIdx.x] = s; __syncthreads();
    for (int st = 128; st > 0; st >>= 1) {
        if (threadIdx.x < st) sm[threadIdx.x] += sm[threadIdx.x + st];
        __syncthreads();
    }
    if (threadIdx.x == 0) g_part[a][blockIdx.x] = sm[0];
}
__global__ void k_scanpart() {
    __shared__ int sm[128];
    int t = threadIdx.x;
    for (int a = 0; a < 2; a++) {
        int v = (t < SCAN_BLK) ? g_part[a][t] : 0;
        sm[t] = v; __syncthreads();
        for (int st = 1; st < 128; st <<= 1) {
            int u = (t >= st) ? sm[t - st] : 0;
            __syncthreads();
            sm[t] += u;
            __syncthreads();
        }
        if (t < SCAN_BLK) g_part[a][t] = sm[t] - v;
        __syncthreads();
    }
}
__global__ void k_write_off() {
    const int a = blockIdx.y;
    int* cnt = a ? g_cur_s : g_cur_d;
    int* off = a ? g_off_s : g_off_d;
    __shared__ int sm[256];
    const int t = threadIdx.x;
    const int i0 = blockIdx.x * 1024 + t * 4;
    int c[4]; int ts = 0;
#pragma unroll
    for (int q = 0; q < 4; q++) { int i = i0 + q; c[q] = (i < NDST) ? cnt[i] : 0; ts += c[q]; }
    sm[t] = ts; __syncthreads();
    for (int st = 1; st < 256; st <<= 1) {
        int u = (t >= st) ? sm[t - st] : 0;
        __syncthreads();
        sm[t] += u;
        __syncthreads();
    }
    int excl = sm[t] - ts + g_part[a][blockIdx.x];
#pragma unroll
    for (int q = 0; q < 4; q++) {
        int i = i0 + q;
        if (i < NDST) {
            off[i] = excl;
            cnt[i] = excl;
            if (i == NDST - 1) off[NDST] = excl + c[q];
            excl += c[q];
        }
    }
}
__global__ void k_place(const int* __restrict__ es, const int* __restrict__ ed) {
    int i = blockIdx.x * blockDim.x + threadIdx.x;
    if (i >= NE) return;
    int s = es[i], d = ed[i];
    int pd = atomicAdd(&g_cur_d[d], 1);
    g_adj_d[pd] = s;
    int ps = atomicAdd(&g_cur_s[s], 1);
    g_adj_s[ps] = d;
}

// ---------------------------------------------------------------------------
// B = [W_self | W_neigh] concat along K
// ---------------------------------------------------------------------------
__global__ void k_prep_B(const float* __restrict__ Wss, const float* __restrict__ Wsn,
                         const float* __restrict__ Wrs, const float* __restrict__ Wrn) {
    int l = blockIdx.x >> 1, d = blockIdx.x & 1;
    const float* Wself  = (d == 0 ? Wss : Wrs) + l * DIM * DIM;
    const float* Wneigh = (d == 0 ? Wsn : Wrn) + l * DIM * DIM;
    for (int i = blockIdx.y * blockDim.x + threadIdx.x; i < DIM * 256; i += blockDim.x * gridDim.y) {
        int n = i >> 8;
        int k = i & 255;
        float v = (k < DIM) ? Wself[n * DIM + k] : Wneigh[n * DIM + (k - DIM)];
        __nv_bfloat16 hi = __float2bfloat16(v);
        __nv_bfloat16 lo = __float2bfloat16(v - __bfloat162float(hi));
        g_Bbf[l][d][0][i] = hi;
        g_Bbf[l][d][1][i] = lo;
    }
}

// ---------------------------------------------------------------------------
// CSR gather: one warp per (node, dir). Mean folded in. Output: bf16 hi/lo planes.
// layer0 reads fp32 x; layer1 reads h hi/lo planes.
// ---------------------------------------------------------------------------
__global__ void __launch_bounds__(256) k_gather(
    int layer, const float* __restrict__ xs, const float* __restrict__ xd)
{
    int w = (blockIdx.x * blockDim.x + threadIdx.x) >> 5;
    if (w >= 2 * NDST) return;
    const int lane = threadIdx.x & 31;
    int node, dir;
    if (w < NDST) { node = w; dir = 0; } else { node = w - NDST; dir = 1; }

    const int *off, *adj; const float* featf;
    const __nv_bfloat16 *fh, *fl;
    __nv_bfloat16 *oh, *ol;
    if (dir == 0) {
        off = g_off_d; adj = g_adj_d;
        featf = xs; fh = g_hs_hi; fl = g_hs_lo;
        oh = g_aggd_hi; ol = g_aggd_lo;
    } else {
        off = g_off_s; adj = g_adj_s;
        featf = xd; fh = g_hd_hi; fl = g_hd_lo;
        oh = g_aggs_hi; ol = g_aggs_lo;
    }

    const int b = off[node], e = off[node + 1];
    const int c = lane * 4;
    float4 acc = make_float4(0.f, 0.f, 0.f, 0.f);
    if (layer == 0) {
        int j = b;
        for (; j + 1 < e; j += 2) {
            int r0 = __ldg(&adj[j]);
            int r1 = __ldg(&adj[j + 1]);
            float4 v0 = *reinterpret_cast<const float4*>(&featf[(size_t)r0 * DIM + c]);
            float4 v1 = *reinterpret_cast<const float4*>(&featf[(size_t)r1 * DIM + c]);
            acc.x += v0.x + v1.x; acc.y += v0.y + v1.y;
            acc.z += v0.z + v1.z; acc.w += v0.w + v1.w;
        }
        if (j < e) {
            int r0 = __ldg(&adj[j]);
            float4 v0 = *reinterpret_cast<const float4*>(&featf[(size_t)r0 * DIM + c]);
            acc.x += v0.x; acc.y += v0.y; acc.z += v0.z; acc.w += v0.w;
        }
    } else {
        for (int j = b; j < e; j++) {
            int r0 = __ldg(&adj[j]);
            const __nv_bfloat162* ph = (const __nv_bfloat162*)&fh[(size_t)r0 * DIM + c];
            const __nv_bfloat162* pl = (const __nv_bfloat162*)&fl[(size_t)r0 * DIM + c];
            __nv_bfloat162 h0 = ph[0], h1 = ph[1], l0 = pl[0], l1 = pl[1];
            float2 fh0 = __bfloat1622float2(h0), fh1 = __bfloat1622float2(h1);
            float2 fl0 = __bfloat1622float2(l0), fl1 = __bfloat1622float2(l1);
            acc.x += fh0.x + fl0.x; acc.y += fh0.y + fl0.y;
            acc.z += fh1.x + fl1.x; acc.w += fh1.y + fl1.y;
        }
    }
    const float s = 1.0f / fmaxf((float)(e - b), 1.0f);
    acc.x *= s; acc.y *= s; acc.z *= s; acc.w *= s;

    uint32_t h0, h1, l0, l1;
    asm("cvt.rn.bf16x2.f32 %0, %1, %2;" : "=r"(h0) : "f"(acc.y), "f"(acc.x));
    float hx = __uint_as_float(h0 << 16), hy = __uint_as_float(h0 & 0xffff0000u);
    asm("cvt.rn.bf16x2.f32 %0, %1, %2;" : "=r"(l0) : "f"(acc.y - hy), "f"(acc.x - hx));
    asm("cvt.rn.bf16x2.f32 %0, %1, %2;" : "=r"(h1) : "f"(acc.w), "f"(acc.z));
    float hz = __uint_as_float(h1 << 16), hw = __uint_as_float(h1 & 0xffff0000u);
    asm("cvt.rn.bf16x2.f32 %0, %1, %2;" : "=r"(l1) : "f"(acc.w - hw), "f"(acc.z - hz));
    *(uint2*)&oh[(size_t)node * DIM + c] = make_uint2(h0, h1);
    *(uint2*)&ol[(size_t)node * DIM + c] = make_uint2(l0, l1);
}

// ---------------------------------------------------------------------------
// Persistent pipelined mma.sync GEMM (3-term hi/lo split).
// B (all 4 chunks, hi/lo) resident in smem per CTA; A double-buffered cp.async.
// SMEM bytes: A stages [0,73728) B chunks [73728,221184) bias [221184,221696)
// ---------------------------------------------------------------------------
#define SPAD 72
#define PLANE_B 18432                 // bytes per 128x64 bf16 plane (pitch 144B)
#define AREG_B 73728                  // A region: 2 stages x 2 planes
#define BREG_B 147456                 // B region: 4 chunks x 2 planes
#define SM_BIAS_B (AREG_B + BREG_B)   // 221184
#define SM_TOTAL (SM_BIAS_B + 512)    // 221696

__device__ __forceinline__ uint32_t smem_u32(const void* p) {
    uint32_t a;
    asm("{ .reg .u64 t; cvta.to.shared.u64 t, %1; cvt.u32.u64 %0, t; }" : "=r"(a) : "l"(p));
    return a;
}
#define CP_ASYNC16(dst, src) \
    asm volatile("cp.async.cg.shared.global [%0], [%1], 16;" :: "r"(dst), "l"(src))
#define CP_COMMIT() asm volatile("cp.async.commit_group;")
#define CP_WAIT1()  asm volatile("cp.async.wait_group 1;")

#define LDSM_X4(r, addr) \
    asm volatile("ldmatrix.sync.aligned.m8n8.x4.shared.b16 {%0,%1,%2,%3}, [%4];" \
        : "=r"((r)[0]), "=r"((r)[1]), "=r"((r)[2]), "=r"((r)[3]) : "r"(addr))

#define MMA_BF16(c, a, b0, b1) \
    asm volatile("mma.sync.aligned.m16n8k16.row.col.f32.bf16.bf16.f32 " \
        "{%0,%1,%2,%3}, {%4,%5,%6,%7}, {%8,%9}, {%0,%1,%2,%3};" \
        : "+f"((c)[0]), "+f"((c)[1]), "+f"((c)[2]), "+f"((c)[3]) \
        : "r"((a)[0]), "r"((a)[1]), "r"((a)[2]), "r"((a)[3]), "r"(b0), "r"(b1))

__global__ void __launch_bounds__(256, 1) k_gemm(
    int layer,
    const float* __restrict__ xs, const float* __restrict__ xd,
    const float* __restrict__ bsh, const float* __restrict__ brv,
    float* __restrict__ dout)
{
    extern __shared__ unsigned char smraw[];
    __nv_bfloat16* sm = (__nv_bfloat16*)smraw;
    float* sbias = (float*)(smraw + SM_BIAS_B);

    const int tid  = threadIdx.x;
    const int wid  = tid >> 5, lane = tid & 31;
    const int dir  = blockIdx.y;
    const int wm   = wid & 1;
    const int wn   = wid >> 1;
    const uint32_t smb = smem_u32(sm);

    const float *Aself_f, *bias;
    const __nv_bfloat16 *Sh, *Sl, *Gh, *Gl;
    __nv_bfloat16 *Oh, *Ol;
    float* outf;
    if (dir == 0) {                       // -> new h_d
        Aself_f = xd; Sh = g_hd_hi; Sl = g_hd_lo;
        Gh = g_aggd_hi; Gl = g_aggd_lo;
        Oh = g_hd_hi; Ol = g_hd_lo;
        bias = bsh + layer * DIM;
        outf = dout + (size_t)NSRC * DIM;
    } else {                              // -> new h_s
        Aself_f = xs; Sh = g_hs_hi; Sl = g_hs_lo;
        Gh = g_aggs_hi; Gl = g_aggs_lo;
        Oh = g_hs_hi; Ol = g_hs_lo;
        bias = brv + layer * DIM;
        outf = dout;
    }
    const __nv_bfloat16* Bhg = g_Bbf[layer][dir][0];
    const __nv_bfloat16* Blg = g_Bbf[layer][dir][1];

    // ---- B: load all 4 chunks (hi/lo) via cp.async, one group ----
#pragma unroll 4
    for (int j = 0; j < 32; j++) {
        int i = j * 256 + tid;            // 8192 x 16B ops
        int pc = i >> 10;                 // plane-chunk 0..7 (c*2+p)
        int cch = pc >> 1, pp = pc & 1;
        int rem = i & 1023;
        int rowi = rem >> 3, piece = rem & 7;
        const __nv_bfloat16* src = (pp ? Blg : Bhg) + rowi * 256 + cch * 64 + piece * 8;
        uint32_t dst = smb + AREG_B + pc * PLANE_B + rowi * 144 + piece * 16;
        CP_ASYNC16(dst, src);
    }
    CP_COMMIT();
    if (tid < DIM) sbias[tid] = bias[tid];

    // fragment address components
    const int a_row_off = (wm * 64 + (lane & 15)) * SPAD + (lane >> 4) * 8;
    const int b_row_off = (wn * 32 + (lane & 7) + (lane >> 4) * 8) * SPAD + ((lane >> 3) & 1) * 8;

    // fp32 self-load mapping (layer 0)
    const int lrow  = tid >> 1;
    const int lhalf = (tid & 1) * 32;

    // --- A issue helpers ---
    auto issue_plane = [&](int tile, int kc, int st) {
        const __nv_bfloat16* ph = (kc < 2) ? Sh : Gh;
        const __nv_bfloat16* pl = (kc < 2) ? Sl : Gl;
        const int col0 = (kc & 1) * 64;
#pragma unroll
        for (int j = 0; j < 8; j++) {
            int i = j * 256 + tid;        // 2048 ops
            int pp = i >> 10;
            int rem = i & 1023;
            int rowi = rem >> 3, piece = rem & 7;
            int r = tile * 128 + rowi; if (r > NDST - 1) r = NDST - 1;
            const __nv_bfloat16* src = (pp ? pl : ph) + (size_t)r * DIM + col0 + piece * 8;
            uint32_t dst = smb + (st * 2 + pp) * PLANE_B + rowi * 144 + piece * 16;
            CP_ASYNC16(dst, src);
        }
    };
    auto issue_f32 = [&](int tile, int kc, int st) {
        int r = tile * 128 + lrow; if (r > NDST - 1) r = NDST - 1;
        const float* src = Aself_f + (size_t)r * DIM + (kc & 1) * 64 + lhalf;
        __nv_bfloat16* ah = sm + (st * 2 + 0) * (PLANE_B / 2) + lrow * SPAD + lhalf;
        __nv_bfloat16* al = sm + (st * 2 + 1) * (PLANE_B / 2) + lrow * SPAD + lhalf;
#pragma unroll
        for (int q = 0; q < 8; q++) {
            float4 v = __ldg((const float4*)src + q);
            uint32_t h0, h1, l0, l1;
            asm("cvt.rn.bf16x2.f32 %0, %1, %2;" : "=r"(h0) : "f"(v.y), "f"(v.x));
            float hx = __uint_as_float(h0 << 16), hy = __uint_as_float(h0 & 0xffff0000u);
            asm("cvt.rn.bf16x2.f32 %0, %1, %2;" : "=r"(l0) : "f"(v.y - hy), "f"(v.x - hx));
            asm("cvt.rn.bf16x2.f32 %0, %1, %2;" : "=r"(h1) : "f"(v.w), "f"(v.z));
            float hz = __uint_as_float(h1 << 16), hw = __uint_as_float(h1 & 0xffff0000u);
            asm("cvt.rn.bf16x2.f32 %0, %1, %2;" : "=r"(l1) : "f"(v.w - hw), "f"(v.z - hz));
            *(uint2*)(ah + 4 * q) = make_uint2(h0, h1);
            *(uint2*)(al + 4 * q) = make_uint2(l0, l1);
        }
    };
    auto issue_A = [&](int tile, int kc, int st) {
        if (layer == 1 || kc >= 2) issue_plane(tile, kc, st);
        else issue_f32(tile, kc, st);
    };

    // ---- persistent tile pipeline ----
    int st = 0;
    issue_A(blockIdx.x, 0, 0);
    CP_COMMIT();

    for (int tile = blockIdx.x; tile < TILES; tile += PCTAS) {
        float acc[4][4][4];
#pragma unroll
        for (int i = 0; i < 4; i++)
#pragma unroll
            for (int j = 0; j < 4; j++)
#pragma unroll
                for (int q = 0; q < 4; q++) acc[i][j][q] = 0.f;

#pragma unroll 1
        for (int kc = 0; kc < 4; kc++) {
            // prefetch next chunk (possibly next tile's chunk 0)
            int ntile = (kc < 3) ? tile : tile + PCTAS;
            int nkc   = (kc < 3) ? kc + 1 : 0;
            if (ntile < TILES) issue_A(ntile, nkc, st ^ 1);
            CP_COMMIT();
            CP_WAIT1();
            __syncthreads();

            const uint32_t aHi = smb + (st * 2) * PLANE_B + 2 * a_row_off;
            const uint32_t aLo = aHi + PLANE_B;
            const uint32_t bHi = smb + AREG_B + (kc * 2) * PLANE_B + 2 * b_row_off;
            const uint32_t bLo = bHi + PLANE_B;
#pragma unroll
            for (int term = 0; term < 3; term++) {
                const uint32_t aBase = (term == 1) ? aLo : aHi;
                const uint32_t bBase = (term == 2) ? bLo : bHi;
#pragma unroll
                for (int k16 = 0; k16 < 4; k16++) {
                    uint32_t a[4][4], b[2][4];
#pragma unroll
                    for (int mt = 0; mt < 4; mt++)
                        LDSM_X4(a[mt], aBase + 2 * (mt * 16 * SPAD + k16 * 16));
#pragma unroll
                    for (int p = 0; p < 2; p++)
                        LDSM_X4(b[p], bBase + 2 * (p * 16 * SPAD + k16 * 16));
#pragma unroll
                    for (int mt = 0; mt < 4; mt++)
#pragma unroll
                        for (int nt = 0; nt < 4; nt++)
                            MMA_BF16(acc[mt][nt], a[mt],
                                     b[nt >> 1][(nt & 1) * 2], b[nt >> 1][(nt & 1) * 2 + 1]);
                }
            }
            __syncthreads();
            st ^= 1;
        }

        // ---- epilogue ----
        const int ebase_r = tile * 128 + wm * 64 + (lane >> 2);
        const int ebase_c = wn * 32 + (lane & 3) * 2;
#pragma unroll
        for (int mt = 0; mt < 4; mt++) {
#pragma unroll
            for (int nt = 0; nt < 4; nt++) {
                const int c = ebase_c + nt * 8;
                const float b0 = sbias[c], b1 = sbias[c + 1];
#pragma unroll
                for (int half = 0; half < 2; half++) {
                    int r = ebase_r + mt * 16 + half * 8;
                    if (r < NDST) {
                        float o0 = fmaxf(acc[mt][nt][half * 2 + 0] + b0, 0.f);
                        float o1 = fmaxf(acc[mt][nt][half * 2 + 1] + b1, 0.f);
                        if (layer == 1) {
                            *(float2*)&outf[(size_t)r * DIM + c] = make_float2(o0, o1);
                        } else {
                            uint32_t h, l;
                            asm("cvt.rn.bf16x2.f32 %0, %1, %2;" : "=r"(h) : "f"(o1), "f"(o0));
                            float hx = __uint_as_float(h << 16), hy = __uint_as_float(h & 0xffff0000u);
                            asm("cvt.rn.bf16x2.f32 %0, %1, %2;" : "=r"(l) : "f"(o1 - hy), "f"(o0 - hx));
                            *(uint32_t*)&Oh[(size_t)r * DIM + c] = h;
                            *(uint32_t*)&Ol[(size_t)r * DIM + c] = l;
                        }
                    }
                }
            }
        }
    }
}

// ---------------------------------------------------------------------------
// Launch
// ---------------------------------------------------------------------------
extern "C" void kernel_launch(void* const* d_in, const int* in_sizes, int n_in,
                              void* d_out, int out_size)
{
    const float* x_src = (const float*)d_in[0];
    const float* x_dst = (const float*)d_in[1];
    const int*   e_src = (const int*)  d_in[2];
    const int*   e_dst = (const int*)  d_in[3];
    const float* Wss   = (const float*)d_in[4];
    const float* Wsn   = (const float*)d_in[5];
    const float* bsh   = (const float*)d_in[6];
    const float* Wrs   = (const float*)d_in[7];
    const float* Wrn   = (const float*)d_in[8];
    const float* brv   = (const float*)d_in[9];
    float* out = (float*)d_out;

    cudaFuncSetAttribute(k_gemm, cudaFuncAttributeMaxDynamicSharedMemorySize, SM_TOTAL);

    // CSR build (graph static per call)
    k_zero_cnt<<<(NDST + 255) / 256, 256>>>();
    k_count<<<(NE + 255) / 256, 256>>>(e_src, e_dst);
    k_blocksum<<<dim3(SCAN_BLK, 2), 256>>>();
    k_scanpart<<<1, 128>>>();
    k_write_off<<<dim3(SCAN_BLK, 2), 256>>>();
    k_place<<<(NE + 255) / 256, 256>>>(e_src, e_dst);
    k_prep_B<<<dim3(4, 8), 256>>>(Wss, Wsn, Wrs, Wrn);

    for (int layer = 0; layer < NLAY; layer++) {
        k_gather<<<(2 * NDST * 32 + 255) / 256, 256>>>(layer, x_src, x_dst);
        k_gemm<<<dim3(PCTAS, 2), 256, SM_TOTAL>>>(layer, x_src, x_dst, bsh, brv, out);
    }
}

// round 7
// speedup vs baseline: 2.1566x; 1.0384x over previous
#include <cuda_runtime.h>
#include <cuda_bf16.h>
#include <cstdint>

// Problem constants
#define NSRC 100000
#define NDST 100000
#define NE   500000
#define DIM  128
#define NLAY 2
#define TILES 782            // ceil(100000/128)
#define PCTAS 74             // persistent CTAs per direction
#define SCAN_BLK 98          // ceil(100000/1024)

// ---------------------------------------------------------------------------
// Scratch (device globals: allocation-free, graph-capture safe)
// ---------------------------------------------------------------------------
// bf16 hi/lo feature planes
__device__ __nv_bfloat16 g_xs_hi[NSRC * DIM], g_xs_lo[NSRC * DIM];
__device__ __nv_bfloat16 g_xd_hi[NDST * DIM], g_xd_lo[NDST * DIM];
__device__ __nv_bfloat16 g_hs_hi[NSRC * DIM], g_hs_lo[NSRC * DIM];
__device__ __nv_bfloat16 g_hd_hi[NDST * DIM], g_hd_lo[NDST * DIM];
__device__ __nv_bfloat16 g_aggs_hi[NSRC * DIM], g_aggs_lo[NSRC * DIM];
__device__ __nv_bfloat16 g_aggd_hi[NDST * DIM], g_aggd_lo[NDST * DIM];
// CSR structures
__device__ int g_off_d[NDST + 1];
__device__ int g_off_s[NSRC + 1];
__device__ int g_cur_d[NDST];
__device__ int g_cur_s[NSRC];
__device__ int g_adj_d[NE];
__device__ int g_adj_s[NE];
__device__ int g_part[2][128];
// bf16 hi/lo weight images: [layer][dir][hi/lo][n=128][k=256]
__device__ __nv_bfloat16 g_Bbf[NLAY][2][2][DIM * 256];

// ---------------------------------------------------------------------------
// hi/lo split helper
// ---------------------------------------------------------------------------
__device__ __forceinline__ void split2(float x, float y, uint32_t& h, uint32_t& l) {
    asm("cvt.rn.bf16x2.f32 %0, %1, %2;" : "=r"(h) : "f"(y), "f"(x));
    float hx = __uint_as_float(h << 16), hy = __uint_as_float(h & 0xffff0000u);
    asm("cvt.rn.bf16x2.f32 %0, %1, %2;" : "=r"(l) : "f"(y - hy), "f"(x - hx));
}

// ---------------------------------------------------------------------------
// CSR build: histogram -> scan -> placement
// ---------------------------------------------------------------------------
__global__ void k_zero_cnt() {
    int i = blockIdx.x * blockDim.x + threadIdx.x;
    if (i < NDST) { g_cur_d[i] = 0; g_cur_s[i] = 0; }
}
__global__ void k_count(const int* __restrict__ es, const int* __restrict__ ed) {
    int i = blockIdx.x * blockDim.x + threadIdx.x;
    if (i < NE) {
        atomicAdd(&g_cur_d[ed[i]], 1);
        atomicAdd(&g_cur_s[es[i]], 1);
    }
}
__global__ void k_blocksum() {
    const int a = blockIdx.y;
    const int* cnt = a ? g_cur_s : g_cur_d;
    __shared__ int sm[256];
    int base = blockIdx.x * 1024 + threadIdx.x * 4;
    int s = 0;
#pragma unroll
    for (int q = 0; q < 4; q++) { int i = base + q; if (i < NDST) s += cnt[i]; }
    sm[threadIdx.x] = s; __syncthreads();
    for (int st = 128; st > 0; st >>= 1) {
        if (threadIdx.x < st) sm[threadIdx.x] += sm[threadIdx.x + st];
        __syncthreads();
    }
    if (threadIdx.x == 0) g_part[a][blockIdx.x] = sm[0];
}
__global__ void k_write_off() {
    const int a = blockIdx.y;
    int* cnt = a ? g_cur_s : g_cur_d;
    int* off = a ? g_off_s : g_off_d;
    __shared__ int sm[256];
    __shared__ int s_pre;
    const int t = threadIdx.x;
    if (t == 0) {                       // serial prefix over <=97 block partials
        int p = 0;
        for (int b2 = 0; b2 < blockIdx.x; b2++) p += __ldg(&g_part[a][b2]);
        s_pre = p;
    }
    const int i0 = blockIdx.x * 1024 + t * 4;
    int c[4]; int ts = 0;
#pragma unroll
    for (int q = 0; q < 4; q++) { int i = i0 + q; c[q] = (i < NDST) ? cnt[i] : 0; ts += c[q]; }
    sm[t] = ts; __syncthreads();
    for (int st = 1; st < 256; st <<= 1) {
        int u = (t >= st) ? sm[t - st] : 0;
        __syncthreads();
        sm[t] += u;
        __syncthreads();
    }
    int excl = sm[t] - ts + s_pre;
#pragma unroll
    for (int q = 0; q < 4; q++) {
        int i = i0 + q;
        if (i < NDST) {
            off[i] = excl;
            cnt[i] = excl;
            if (i == NDST - 1) off[NDST] = excl + c[q];
            excl += c[q];
        }
    }
}
__global__ void k_place(const int* __restrict__ es, const int* __restrict__ ed) {
    int i = blockIdx.x * blockDim.x + threadIdx.x;
    if (i >= NE) return;
    int s = es[i], d = ed[i];
    int pd = atomicAdd(&g_cur_d[d], 1);
    g_adj_d[pd] = s;
    int ps = atomicAdd(&g_cur_s[s], 1);
    g_adj_s[ps] = d;
}

// ---------------------------------------------------------------------------
// x -> bf16 hi/lo planes (once; x static across layers)
// ---------------------------------------------------------------------------
__global__ void k_prep_X(const float* __restrict__ xs, const float* __restrict__ xd) {
    int i = blockIdx.x * blockDim.x + threadIdx.x;   // float4 index
    const int n4 = NSRC * DIM / 4;
    if (i >= n4) return;
    float4 v = __ldg((const float4*)xs + i);
    uint32_t h0, h1, l0, l1;
    split2(v.x, v.y, h0, l0); split2(v.z, v.w, h1, l1);
    *(uint2*)&g_xs_hi[i * 4] = make_uint2(h0, h1);
    *(uint2*)&g_xs_lo[i * 4] = make_uint2(l0, l1);
    v = __ldg((const float4*)xd + i);
    split2(v.x, v.y, h0, l0); split2(v.z, v.w, h1, l1);
    *(uint2*)&g_xd_hi[i * 4] = make_uint2(h0, h1);
    *(uint2*)&g_xd_lo[i * 4] = make_uint2(l0, l1);
}

// ---------------------------------------------------------------------------
// B = [W_self | W_neigh] concat along K
// ---------------------------------------------------------------------------
__global__ void k_prep_B(const float* __restrict__ Wss, const float* __restrict__ Wsn,
                         const float* __restrict__ Wrs, const float* __restrict__ Wrn) {
    int l = blockIdx.x >> 1, d = blockIdx.x & 1;
    const float* Wself  = (d == 0 ? Wss : Wrs) + l * DIM * DIM;
    const float* Wneigh = (d == 0 ? Wsn : Wrn) + l * DIM * DIM;
    for (int i = blockIdx.y * blockDim.x + threadIdx.x; i < DIM * 256; i += blockDim.x * gridDim.y) {
        int n = i >> 8;
        int k = i & 255;
        float v = (k < DIM) ? Wself[n * DIM + k] : Wneigh[n * DIM + (k - DIM)];
        __nv_bfloat16 hi = __float2bfloat16(v);
        __nv_bfloat16 lo = __float2bfloat16(v - __bfloat162float(hi));
        g_Bbf[l][d][0][i] = hi;
        g_Bbf[l][d][1][i] = lo;
    }
}

// ---------------------------------------------------------------------------
// CSR gather: one warp per (node, dir), mean folded in, bf16 hi/lo plane output
// ---------------------------------------------------------------------------
__device__ __forceinline__ void acc_bf4(float4& acc, uint2 H, uint2 L) {
    float2 fh0 = __bfloat1622float2(*(__nv_bfloat162*)&H.x);
    float2 fh1 = __bfloat1622float2(*(__nv_bfloat162*)&H.y);
    float2 fl0 = __bfloat1622float2(*(__nv_bfloat162*)&L.x);
    float2 fl1 = __bfloat1622float2(*(__nv_bfloat162*)&L.y);
    acc.x += fh0.x + fl0.x; acc.y += fh0.y + fl0.y;
    acc.z += fh1.x + fl1.x; acc.w += fh1.y + fl1.y;
}

__global__ void __launch_bounds__(256) k_gather(
    int layer, const float* __restrict__ xs, const float* __restrict__ xd)
{
    int w = (blockIdx.x * blockDim.x + threadIdx.x) >> 5;
    if (w >= 2 * NDST) return;
    const int lane = threadIdx.x & 31;
    int node, dir;
    if (w < NDST) { node = w; dir = 0; } else { node = w - NDST; dir = 1; }

    const int *off, *adj; const float* featf;
    const __nv_bfloat16 *fh, *fl;
    __nv_bfloat16 *oh, *ol;
    if (dir == 0) {
        off = g_off_d; adj = g_adj_d;
        featf = xs; fh = g_hs_hi; fl = g_hs_lo;
        oh = g_aggd_hi; ol = g_aggd_lo;
    } else {
        off = g_off_s; adj = g_adj_s;
        featf = xd; fh = g_hd_hi; fl = g_hd_lo;
        oh = g_aggs_hi; ol = g_aggs_lo;
    }

    const int b = off[node], e = off[node + 1];
    const int c = lane * 4;
    float4 acc = make_float4(0.f, 0.f, 0.f, 0.f);
    if (layer == 0) {
        int j = b;
        for (; j + 1 < e; j += 2) {
            int r0 = __ldg(&adj[j]);
            int r1 = __ldg(&adj[j + 1]);
            float4 v0 = *reinterpret_cast<const float4*>(&featf[(size_t)r0 * DIM + c]);
            float4 v1 = *reinterpret_cast<const float4*>(&featf[(size_t)r1 * DIM + c]);
            acc.x += v0.x + v1.x; acc.y += v0.y + v1.y;
            acc.z += v0.z + v1.z; acc.w += v0.w + v1.w;
        }
        if (j < e) {
            int r0 = __ldg(&adj[j]);
            float4 v0 = *reinterpret_cast<const float4*>(&featf[(size_t)r0 * DIM + c]);
            acc.x += v0.x; acc.y += v0.y; acc.z += v0.z; acc.w += v0.w;
        }
    } else {
        int j = b;
        for (; j + 1 < e; j += 2) {                     // 4 loads in flight
            int r0 = __ldg(&adj[j]);
            int r1 = __ldg(&adj[j + 1]);
            uint2 H0 = __ldg((const uint2*)&fh[(size_t)r0 * DIM + c]);
            uint2 L0 = __ldg((const uint2*)&fl[(size_t)r0 * DIM + c]);
            uint2 H1 = __ldg((const uint2*)&fh[(size_t)r1 * DIM + c]);
            uint2 L1 = __ldg((const uint2*)&fl[(size_t)r1 * DIM + c]);
            acc_bf4(acc, H0, L0);
            acc_bf4(acc, H1, L1);
        }
        if (j < e) {
            int r0 = __ldg(&adj[j]);
            uint2 H0 = __ldg((const uint2*)&fh[(size_t)r0 * DIM + c]);
            uint2 L0 = __ldg((const uint2*)&fl[(size_t)r0 * DIM + c]);
            acc_bf4(acc, H0, L0);
        }
    }
    const float s = 1.0f / fmaxf((float)(e - b), 1.0f);
    acc.x *= s; acc.y *= s; acc.z *= s; acc.w *= s;

    uint32_t h0, h1, l0, l1;
    split2(acc.x, acc.y, h0, l0);
    split2(acc.z, acc.w, h1, l1);
    *(uint2*)&oh[(size_t)node * DIM + c] = make_uint2(h0, h1);
    *(uint2*)&ol[(size_t)node * DIM + c] = make_uint2(l0, l1);
}

// ---------------------------------------------------------------------------
// Persistent pipelined mma.sync GEMM (3-term hi/lo split, unique-fragment loads)
// ---------------------------------------------------------------------------
#define SPAD 72
#define PLANE_B 18432                 // bytes per 128x64 bf16 plane (pitch 144B)
#define AREG_B 73728                  // A region: 2 stages x 2 planes
#define BREG_B 147456                 // B region: 4 chunks x 2 planes
#define SM_BIAS_B (AREG_B + BREG_B)
#define SM_TOTAL (SM_BIAS_B + 512)

__device__ __forceinline__ uint32_t smem_u32(const void* p) {
    uint32_t a;
    asm("{ .reg .u64 t; cvta.to.shared.u64 t, %1; cvt.u32.u64 %0, t; }" : "=r"(a) : "l"(p));
    return a;
}
#define CP_ASYNC16(dst, src) \
    asm volatile("cp.async.cg.shared.global [%0], [%1], 16;" :: "r"(dst), "l"(src))
#define CP_COMMIT() asm volatile("cp.async.commit_group;")
#define CP_WAIT1()  asm volatile("cp.async.wait_group 1;")

#define LDSM_X4(r, addr) \
    asm volatile("ldmatrix.sync.aligned.m8n8.x4.shared.b16 {%0,%1,%2,%3}, [%4];" \
        : "=r"((r)[0]), "=r"((r)[1]), "=r"((r)[2]), "=r"((r)[3]) : "r"(addr))

#define MMA_BF16(c, a, b0, b1) \
    asm volatile("mma.sync.aligned.m16n8k16.row.col.f32.bf16.bf16.f32 " \
        "{%0,%1,%2,%3}, {%4,%5,%6,%7}, {%8,%9}, {%0,%1,%2,%3};" \
        : "+f"((c)[0]), "+f"((c)[1]), "+f"((c)[2]), "+f"((c)[3]) \
        : "r"((a)[0]), "r"((a)[1]), "r"((a)[2]), "r"((a)[3]), "r"(b0), "r"(b1))

__global__ void __launch_bounds__(256, 1) k_gemm(
    int layer, const float* __restrict__ bsh, const float* __restrict__ brv,
    float* __restrict__ dout)
{
    extern __shared__ unsigned char smraw[];
    __nv_bfloat16* sm = (__nv_bfloat16*)smraw;
    float* sbias = (float*)(smraw + SM_BIAS_B);

    const int tid  = threadIdx.x;
    const int wid  = tid >> 5, lane = tid & 31;
    const int dir  = blockIdx.y;
    const int wm   = wid & 1;
    const int wn   = wid >> 1;
    const uint32_t smb = smem_u32(sm);

    const float* bias;
    const __nv_bfloat16 *Sh, *Sl, *Gh, *Gl;
    __nv_bfloat16 *Oh, *Ol;
    float* outf;
    if (dir == 0) {                       // -> new h_d (self = dst side)
        Sh = layer ? g_hd_hi : g_xd_hi;  Sl = layer ? g_hd_lo : g_xd_lo;
        Gh = g_aggd_hi; Gl = g_aggd_lo;
        Oh = g_hd_hi; Ol = g_hd_lo;
        bias = bsh + layer * DIM;
        outf = dout + (size_t)NSRC * DIM;
    } else {                              // -> new h_s (self = src side)
        Sh = layer ? g_hs_hi : g_xs_hi;  Sl = layer ? g_hs_lo : g_xs_lo;
        Gh = g_aggs_hi; Gl = g_aggs_lo;
        Oh = g_hs_hi; Ol = g_hs_lo;
        bias = brv + layer * DIM;
        outf = dout;
    }
    const __nv_bfloat16* Bhg = g_Bbf[layer][dir][0];
    const __nv_bfloat16* Blg = g_Bbf[layer][dir][1];

    // ---- B: load all 4 chunks (hi/lo), one cp.async group ----
#pragma unroll 4
    for (int j = 0; j < 32; j++) {
        int i = j * 256 + tid;
        int pc = i >> 10;
        int cch = pc >> 1, pp = pc & 1;
        int rem = i & 1023;
        int rowi = rem >> 3, piece = rem & 7;
        const __nv_bfloat16* src = (pp ? Blg : Bhg) + rowi * 256 + cch * 64 + piece * 8;
        uint32_t dst = smb + AREG_B + pc * PLANE_B + rowi * 144 + piece * 16;
        CP_ASYNC16(dst, src);
    }
    CP_COMMIT();
    if (tid < DIM) sbias[tid] = bias[tid];

    const int a_row_off = (wm * 64 + (lane & 15)) * SPAD + (lane >> 4) * 8;
    const int b_row_off = (wn * 32 + (lane & 7) + (lane >> 4) * 8) * SPAD + ((lane >> 3) & 1) * 8;

    auto issue_A = [&](int tile, int kc, int st) {
        const __nv_bfloat16* ph = (kc < 2) ? Sh : Gh;
        const __nv_bfloat16* pl = (kc < 2) ? Sl : Gl;
        const int col0 = (kc & 1) * 64;
#pragma unroll
        for (int j = 0; j < 8; j++) {
            int i = j * 256 + tid;
            int pp = i >> 10;
            int rem = i & 1023;
            int rowi = rem >> 3, piece = rem & 7;
            int r = tile * 128 + rowi; if (r > NDST - 1) r = NDST - 1;
            const __nv_bfloat16* src = (pp ? pl : ph) + (size_t)r * DIM + col0 + piece * 8;
            uint32_t dst = smb + (st * 2 + pp) * PLANE_B + rowi * 144 + piece * 16;
            CP_ASYNC16(dst, src);
        }
    };

    int st = 0;
    issue_A(blockIdx.x, 0, 0);
    CP_COMMIT();

    for (int tile = blockIdx.x; tile < TILES; tile += PCTAS) {
        float acc[4][4][4];
#pragma unroll
        for (int i = 0; i < 4; i++)
#pragma unroll
            for (int j = 0; j < 4; j++)
#pragma unroll
                for (int q = 0; q < 4; q++) acc[i][j][q] = 0.f;

#pragma unroll 1
        for (int kc = 0; kc < 4; kc++) {
            int ntile = (kc < 3) ? tile : tile + PCTAS;
            int nkc   = (kc < 3) ? kc + 1 : 0;
            if (ntile < TILES) issue_A(ntile, nkc, st ^ 1);
            CP_COMMIT();
            CP_WAIT1();
            __syncthreads();

            const uint32_t aHi = smb + (st * 2) * PLANE_B + 2 * a_row_off;
            const uint32_t aLo = aHi + PLANE_B;
            const uint32_t bHi = smb + AREG_B + (kc * 2) * PLANE_B + 2 * b_row_off;
            const uint32_t bLo = bHi + PLANE_B;
#pragma unroll
            for (int k16 = 0; k16 < 4; k16++) {
                // load unique fragments once: a_hi, a_lo, b_hi, b_lo
                uint32_t ah[4][4], al[4][4], bh[2][4], bl[2][4];
#pragma unroll
                for (int mt = 0; mt < 4; mt++) {
                    LDSM_X4(ah[mt], aHi + 2 * (mt * 16 * SPAD + k16 * 16));
                    LDSM_X4(al[mt], aLo + 2 * (mt * 16 * SPAD + k16 * 16));
                }
#pragma unroll
                for (int p = 0; p < 2; p++) {
                    LDSM_X4(bh[p], bHi + 2 * (p * 16 * SPAD + k16 * 16));
                    LDSM_X4(bl[p], bLo + 2 * (p * 16 * SPAD + k16 * 16));
                }
#pragma unroll
                for (int mt = 0; mt < 4; mt++)
#pragma unroll
                    for (int nt = 0; nt < 4; nt++) {
                        uint32_t* BH = &bh[nt >> 1][(nt & 1) * 2];
                        uint32_t* BL = &bl[nt >> 1][(nt & 1) * 2];
                        MMA_BF16(acc[mt][nt], ah[mt], BH[0], BH[1]);   // hi*hi
                        MMA_BF16(acc[mt][nt], al[mt], BH[0], BH[1]);   // lo*hi
                        MMA_BF16(acc[mt][nt], ah[mt], BL[0], BL[1]);   // hi*lo
                    }
            }
            __syncthreads();
            st ^= 1;
        }

        // ---- epilogue ----
        const int ebase_r = tile * 128 + wm * 64 + (lane >> 2);
        const int ebase_c = wn * 32 + (lane & 3) * 2;
#pragma unroll
        for (int mt = 0; mt < 4; mt++) {
#pragma unroll
            for (int nt = 0; nt < 4; nt++) {
                const int c = ebase_c + nt * 8;
                const float b0 = sbias[c], b1 = sbias[c + 1];
#pragma unroll
                for (int half = 0; half < 2; half++) {
                    int r = ebase_r + mt * 16 + half * 8;
                    if (r < NDST) {
                        float o0 = fmaxf(acc[mt][nt][half * 2 + 0] + b0, 0.f);
                        float o1 = fmaxf(acc[mt][nt][half * 2 + 1] + b1, 0.f);
                        if (layer == 1) {
                            *(float2*)&outf[(size_t)r * DIM + c] = make_float2(o0, o1);
                        } else {
                            uint32_t h, l;
                            split2(o0, o1, h, l);
                            *(uint32_t*)&Oh[(size_t)r * DIM + c] = h;
                            *(uint32_t*)&Ol[(size_t)r * DIM + c] = l;
                        }
                    }
                }
            }
        }
    }
}

// ---------------------------------------------------------------------------
// Launch
// ---------------------------------------------------------------------------
extern "C" void kernel_launch(void* const* d_in, const int* in_sizes, int n_in,
                              void* d_out, int out_size)
{
    const float* x_src = (const float*)d_in[0];
    const float* x_dst = (const float*)d_in[1];
    const int*   e_src = (const int*)  d_in[2];
    const int*   e_dst = (const int*)  d_in[3];
    const float* Wss   = (const float*)d_in[4];
    const float* Wsn   = (const float*)d_in[5];
    const float* bsh   = (const float*)d_in[6];
    const float* Wrs   = (const float*)d_in[7];
    const float* Wrn   = (const float*)d_in[8];
    const float* brv   = (const float*)d_in[9];
    float* out = (float*)d_out;

    cudaFuncSetAttribute(k_gemm, cudaFuncAttributeMaxDynamicSharedMemorySize, SM_TOTAL);

    // CSR build + precomputation
    k_zero_cnt<<<(NDST + 255) / 256, 256>>>();
    k_count<<<(NE + 255) / 256, 256>>>(e_src, e_dst);
    k_blocksum<<<dim3(SCAN_BLK, 2), 256>>>();
    k_write_off<<<dim3(SCAN_BLK, 2), 256>>>();
    k_place<<<(NE + 255) / 256, 256>>>(e_src, e_dst);
    k_prep_B<<<dim3(4, 8), 256>>>(Wss, Wsn, Wrs, Wrn);
    k_prep_X<<<(NSRC * DIM / 4 + 255) / 256, 256>>>(x_src, x_dst);

    for (int layer = 0; layer < NLAY; layer++) {
        k_gather<<<(2 * NDST * 32 + 255) / 256, 256>>>(layer, x_src, x_dst);
        k_gemm<<<dim3(PCTAS, 2), 256, SM_TOTAL>>>(layer, bsh, brv, out);
    }
}